// round 15
// baseline (speedup 1.0000x reference)
#include <cuda_runtime.h>

// y[b,t,c*S+s] = x[b,t,c] * w[c*S+s]
// B=512, T=128, C=128, S=32, OUT_DIM=4096. Output = 1 GiB fp32, write-bound.
//
// R6: persistent grid-stride kernel. 1216 CTAs (8/SM), each loops over ~27
// tiles of 2 output rows (2048 float4s). x is double-buffered in smem and the
// next tile's LDG issues BEFORE the current tile's store burst, so the store
// stream never stalls on a global load. w lives in registers (period-4
// pattern), loaded once per CTA.

#define THREADS      256
#define F4_PER_TILE  2048            // 2 rows * 1024 float4
#define ITERS        8               // 2048 / 256
#define GRID         1216            // 8 CTAs/SM * 152 SMs (GB300)

__global__ __launch_bounds__(THREADS, 8)
void csi_embedding_kernel(const float*  __restrict__ x,
                          const float4* __restrict__ w4,
                          float4*       __restrict__ out4,
                          int ntiles)
{
    __shared__ float s_x[2][THREADS];

    const int tid = threadIdx.x;

    // w registers: 4 distinct float4s per thread, loaded once per CTA
    const float4 wr0 = __ldg(&w4[0 * THREADS + tid]);
    const float4 wr1 = __ldg(&w4[1 * THREADS + tid]);
    const float4 wr2 = __ldg(&w4[2 * THREADS + tid]);
    const float4 wr3 = __ldg(&w4[3 * THREADS + tid]);

    int t = blockIdx.x;
    if (t >= ntiles) return;

    // Prime buffer 0 with tile t's x (256 consecutive floats, coalesced)
    s_x[0][tid] = __ldg(&x[t * THREADS + tid]);
    __syncthreads();

    int buf = 0;
    for (; t < ntiles; t += GRID) {
        const int tn = t + GRID;
        float xn = 0.0f;
        const bool has_next = (tn < ntiles);
        if (has_next)
            xn = __ldg(&x[tn * THREADS + tid]);   // issued before store burst

        const long long base = (long long)t * F4_PER_TILE;
        const float* sx = s_x[buf];

        #pragma unroll
        for (int k = 0; k < ITERS; k++) {
            // pos = k*256 + tid; x idx = pos>>3 = k*32 + (tid>>3)
            float xs = sx[k * 32 + (tid >> 3)];   // broadcast across 8 lanes

            float4 wv;
            switch (k & 3) {
                case 0: wv = wr0; break;
                case 1: wv = wr1; break;
                case 2: wv = wr2; break;
                default: wv = wr3; break;
            }

            float4 r;
            r.x = xs * wv.x;
            r.y = xs * wv.y;
            r.z = xs * wv.z;
            r.w = xs * wv.w;
            __stcs(&out4[base + k * THREADS + tid], r);
        }

        if (has_next)
            s_x[buf ^ 1][tid] = xn;
        __syncthreads();
        buf ^= 1;
    }
}

extern "C" void kernel_launch(void* const* d_in, const int* in_sizes, int n_in,
                              void* d_out, int out_size)
{
    const float*  x  = (const float*)d_in[0];
    const float4* w4 = (const float4*)d_in[1];
    float4* out4 = (float4*)d_out;

    int ntiles = (out_size / 4) / F4_PER_TILE;    // 32768
    csi_embedding_kernel<<<GRID, THREADS>>>(x, w4, out4, ntiles);
}

// round 16
// speedup vs baseline: 1.1528x; 1.1528x over previous
#include <cuda_runtime.h>

// y[b,t,c*S+s] = x[b,t,c] * w[c*S+s]
// B=512, T=128, C=128, S=32, OUT_DIM=4096. Output = 1 GiB fp32, write-bound.
//
// R16 = R2 shape (2 rows/block, 256 thr, 32768 blocks, .cs stores, w staged in
// smem) but warp-decoupled x: each warp owns a 32-channel chunk of one row,
// loads its 32 x floats with ONE coalesced LDG (issued first, overlapping the
// barrier), and broadcasts via __shfl_sync. The single __syncthreads now only
// gates the w staging (L1-hit, fast) — warps start storing the moment their
// own x lands instead of waiting for the block's slowest x load.

#define THREADS 256

__global__ __launch_bounds__(THREADS, 8)
void csi_embedding_kernel(const float*  __restrict__ x,
                          const float4* __restrict__ w4,
                          float4*       __restrict__ out4)
{
    __shared__ float4 s_w[1024];             // 16 KiB: full w table

    const int tid  = threadIdx.x;
    const int lane = tid & 31;
    const int wid  = tid >> 5;               // 8 warps
    const int row  = wid >> 2;               // 0..1  (local row)
    const int c0   = (wid & 3) << 5;         // 0,32,64,96 (channel base)

    // x first: the long pole (DRAM on first touch). One coalesced 128B LDG
    // per warp: 32 consecutive channels of this warp's row.
    const float xv = __ldg(&x[blockIdx.x * 256 + row * 128 + c0 + lane]);

    // Stage w cooperatively (L1-hit after the first wave of blocks).
    #pragma unroll
    for (int k = 0; k < 4; k++)
        s_w[k * THREADS + tid] = __ldg(&w4[k * THREADS + tid]);

    __syncthreads();                         // gates only w (fast)

    // Warp's output window: 256 consecutive float4s (32 channels x 8 f4).
    const long long base = (long long)blockIdx.x * 2048 + row * 1024 + c0 * 8;

    #pragma unroll
    for (int k = 0; k < 8; k++) {
        // float4 m = k*32+lane within chunk; channel offset = m>>3 = k*4+(lane>>3)
        float  xs = __shfl_sync(0xffffffffu, xv, k * 4 + (lane >> 3));
        float4 wv = s_w[c0 * 8 + k * 32 + lane];   // conflict-free LDS.128

        float4 r;
        r.x = xs * wv.x;
        r.y = xs * wv.y;
        r.z = xs * wv.z;
        r.w = xs * wv.w;
        __stcs(&out4[base + k * 32 + lane], r);    // coalesced 512B streaming
    }
}

extern "C" void kernel_launch(void* const* d_in, const int* in_sizes, int n_in,
                              void* d_out, int out_size)
{
    const float*  x  = (const float*)d_in[0];
    const float4* w4 = (const float4*)d_in[1];
    float4* out4 = (float4*)d_out;

    // out_size floats / (2 rows * 4096) per block = 32768 blocks
    int blocks = out_size / 8192;
    csi_embedding_kernel<<<blocks, THREADS>>>(x, w4, out4);
}